// round 2
// baseline (speedup 1.0000x reference)
#include <cuda_runtime.h>
#include <math.h>

// ---------------- problem constants ----------------
#define T_TOK 4096
#define D_DIM 1024
#define E_NUM 8
#define F_DIM 4096
#define G1_N  256
#define G2_N  64
#define MAXPAIRS (T_TOK * 2)   // top-2 => exactly 2*T pairs

// ---------------- device scratch (no allocs allowed) ----------------
__device__ float g_g1[T_TOK * G1_N];            // 4 MB
__device__ float g_g2[T_TOK * G2_N];            // 1 MB
__device__ float g_act[(size_t)MAXPAIRS * F_DIM]; // 134 MB intermediate activations
__device__ int   g_topi[T_TOK * 2];
__device__ float g_topw[T_TOK * 2];
__device__ int   g_pair_token[MAXPAIRS];
__device__ float g_pair_w[MAXPAIRS];
__device__ int   g_counts[E_NUM];
__device__ int   g_offsets[E_NUM];

// ---------------- helpers ----------------
__device__ __forceinline__ float gelu_tanh(float x) {
    // jax.nn.gelu default (approximate=True)
    float x3 = x * x * x;
    float u = 0.7978845608028654f * (x + 0.044715f * x3);
    return 0.5f * x * (1.0f + tanhf(u));
}

// ---------------- zero the dense output region ----------------
__global__ void zero_out_kernel(float* __restrict__ out, int n4) {
    int i = blockIdx.x * blockDim.x + threadIdx.x;
    if (i < n4) {
        ((float4*)out)[i] = make_float4(0.f, 0.f, 0.f, 0.f);
    }
}

// ---------------- generic dense GEMM + bias + relu (router layers 1,2) ----
// C[M,N] = relu(A[M,K] @ B[K,N] + bias[N]).  M % 128 == 0, K % 8 == 0.
__global__ void gemm_bias_relu(const float* __restrict__ A,
                               const float* __restrict__ B,
                               const float* __restrict__ bias,
                               float* __restrict__ C,
                               int M, int N, int K) {
    const int BM = 128, BN = 128, BK = 8;
    __shared__ float As[BK][BM];
    __shared__ float Bs[BK][BN];
    int tid = threadIdx.x;
    int m0 = blockIdx.y * BM, n0 = blockIdx.x * BN;
    int tx = tid % 16, ty = tid / 16;
    int arow = tid >> 1, acol = (tid & 1) * 4;
    int brow = tid >> 5, bcol = (tid & 31) * 4;
    float acc[8][8];
    #pragma unroll
    for (int i = 0; i < 8; i++)
        #pragma unroll
        for (int j = 0; j < 8; j++) acc[i][j] = 0.f;

    const float* aptr = A + (size_t)(m0 + arow) * K + acol;
    for (int k0 = 0; k0 < K; k0 += BK) {
        float4 av = *(const float4*)(aptr + k0);
        As[acol + 0][arow] = av.x;
        As[acol + 1][arow] = av.y;
        As[acol + 2][arow] = av.z;
        As[acol + 3][arow] = av.w;
        float4 bv = make_float4(0.f, 0.f, 0.f, 0.f);
        if (n0 + bcol < N)
            bv = *(const float4*)(B + (size_t)(k0 + brow) * N + n0 + bcol);
        *(float4*)&Bs[brow][bcol] = bv;
        __syncthreads();
        #pragma unroll
        for (int k = 0; k < BK; k++) {
            float ra[8], rb[8];
            #pragma unroll
            for (int i = 0; i < 8; i++) ra[i] = As[k][ty * 8 + i];
            #pragma unroll
            for (int j = 0; j < 8; j++) rb[j] = Bs[k][tx * 8 + j];
            #pragma unroll
            for (int i = 0; i < 8; i++)
                #pragma unroll
                for (int j = 0; j < 8; j++)
                    acc[i][j] = fmaf(ra[i], rb[j], acc[i][j]);
        }
        __syncthreads();
    }
    #pragma unroll
    for (int i = 0; i < 8; i++) {
        int m = m0 + ty * 8 + i;
        #pragma unroll
        for (int j = 0; j < 8; j++) {
            int n = n0 + tx * 8 + j;
            if (n < N) {
                float v = acc[i][j] + bias[n];
                C[(size_t)m * N + n] = fmaxf(v, 0.f);
            }
        }
    }
}

// ---------------- router final: logits, top-2, normalized weights --------
__global__ void router_final(const float* __restrict__ gw3,
                             float* __restrict__ out_logits) {
    int t = blockIdx.x * blockDim.x + threadIdx.x;
    if (t >= T_TOK) return;
    float l[E_NUM];
    #pragma unroll
    for (int e = 0; e < E_NUM; e++) l[e] = 0.f;
    const float* g = g_g2 + (size_t)t * G2_N;
    for (int k = 0; k < G2_N; k++) {
        float gv = g[k];
        #pragma unroll
        for (int e = 0; e < E_NUM; e++)
            l[e] = fmaf(gv, gw3[k * E_NUM + e], l[e]);
    }
    #pragma unroll
    for (int e = 0; e < E_NUM; e++) out_logits[(size_t)t * E_NUM + e] = l[e];
    // top-2 of logits (== top-2 of softmax probs); jax top_k keeps earliest index on ties
    int i0 = 0; float v0 = l[0];
    #pragma unroll
    for (int e = 1; e < E_NUM; e++) { if (l[e] > v0) { v0 = l[e]; i0 = e; } }
    int i1 = -1; float v1 = -3.4e38f;
    #pragma unroll
    for (int e = 0; e < E_NUM; e++) { if (e != i0 && l[e] > v1) { v1 = l[e]; i1 = e; } }
    // normalized weights: softmax denominator cancels
    float e1 = expf(v1 - v0);
    float inv = 1.f / (1.f + e1);
    g_topi[2 * t] = i0;  g_topi[2 * t + 1] = i1;
    g_topw[2 * t] = inv; g_topw[2 * t + 1] = e1 * inv;
}

// ---------------- deterministic per-expert pair lists (counting sort) ----
__global__ void build_pairs() {
    __shared__ int s_cnt[E_NUM];
    __shared__ int s_off[E_NUM];
    int tid = threadIdx.x, wid = tid >> 5, lane = tid & 31;
    if (wid < E_NUM) {
        int e = wid, cnt = 0;
        for (int base = 0; base < T_TOK; base += 32) {
            int t = base + lane;
            bool c = (g_topi[2 * t] == e) || (g_topi[2 * t + 1] == e);
            unsigned b = __ballot_sync(0xffffffffu, c);
            cnt += __popc(b);
        }
        if (lane == 0) s_cnt[e] = cnt;
    }
    __syncthreads();
    if (tid == 0) {
        int off = 0;
        for (int e = 0; e < E_NUM; e++) {
            s_off[e] = off; g_offsets[e] = off; g_counts[e] = s_cnt[e];
            off += s_cnt[e];
        }
    }
    __syncthreads();
    if (wid < E_NUM) {
        int e = wid, pos = s_off[e];
        for (int base = 0; base < T_TOK; base += 32) {
            int t = base + lane;
            bool c0 = (g_topi[2 * t] == e);
            bool c  = c0 || (g_topi[2 * t + 1] == e);
            unsigned b = __ballot_sync(0xffffffffu, c);
            int idx = pos + __popc(b & ((1u << lane) - 1u));
            if (c) {
                g_pair_token[idx] = t;
                g_pair_w[idx] = c0 ? g_topw[2 * t] : g_topw[2 * t + 1];
            }
            pos += __popc(b);
        }
    }
}

// ---------------- pass A: act = gelu(gather(h) @ w1[e] + b1[e]) ----------
// grid: x = F/128 (32), y = E*32 (expert-local m-tiles, fixed worst case)
__global__ void expert_gemm1(const float* __restrict__ h,
                             const float* __restrict__ w1,
                             const float* __restrict__ b1) {
    const int BM = 128, BN = 128, BK = 8;
    int gt = blockIdx.y;
    int e = gt >> 5;
    int m0 = (gt & 31) * BM;
    int cnt = g_counts[e];
    if (m0 >= cnt) return;
    int off = g_offsets[e];
    int n0 = blockIdx.x * BN;
    const float* B = w1 + (size_t)e * D_DIM * F_DIM;

    __shared__ float As[BK][BM];
    __shared__ float Bs[BK][BN];
    int tid = threadIdx.x;
    int arow = tid >> 1, acol = (tid & 1) * 4;
    int brow = tid >> 5, bcol = (tid & 31) * 4;
    int tx = tid % 16, ty = tid / 16;

    bool avalid = (m0 + arow) < cnt;
    int tokenA = avalid ? g_pair_token[off + m0 + arow] : 0;
    const float* aptr = h + (size_t)tokenA * D_DIM + acol;
    const float* bptr = B + (size_t)brow * F_DIM + n0 + bcol;

    float acc[8][8];
    #pragma unroll
    for (int i = 0; i < 8; i++)
        #pragma unroll
        for (int j = 0; j < 8; j++) acc[i][j] = 0.f;

    for (int k0 = 0; k0 < D_DIM; k0 += BK) {
        float4 av = *(const float4*)(aptr + k0);
        As[acol + 0][arow] = av.x;
        As[acol + 1][arow] = av.y;
        As[acol + 2][arow] = av.z;
        As[acol + 3][arow] = av.w;
        float4 bv = *(const float4*)(bptr + (size_t)k0 * F_DIM);
        *(float4*)&Bs[brow][bcol] = bv;
        __syncthreads();
        #pragma unroll
        for (int k = 0; k < BK; k++) {
            float ra[8], rb[8];
            #pragma unroll
            for (int i = 0; i < 8; i++) ra[i] = As[k][ty * 8 + i];
            #pragma unroll
            for (int j = 0; j < 8; j++) rb[j] = Bs[k][tx * 8 + j];
            #pragma unroll
            for (int i = 0; i < 8; i++)
                #pragma unroll
                for (int j = 0; j < 8; j++)
                    acc[i][j] = fmaf(ra[i], rb[j], acc[i][j]);
        }
        __syncthreads();
    }

    #pragma unroll
    for (int i = 0; i < 8; i++) {
        int r = ty * 8 + i;
        if (m0 + r < cnt) {
            size_t pi = (size_t)(off + m0 + r);
            #pragma unroll
            for (int j = 0; j < 8; j += 4) {
                int n = n0 + tx * 8 + j;
                float4 v;
                v.x = gelu_tanh(acc[i][j + 0] + b1[e * F_DIM + n + 0]);
                v.y = gelu_tanh(acc[i][j + 1] + b1[e * F_DIM + n + 1]);
                v.z = gelu_tanh(acc[i][j + 2] + b1[e * F_DIM + n + 2]);
                v.w = gelu_tanh(acc[i][j + 3] + b1[e * F_DIM + n + 3]);
                *(float4*)&g_act[pi * F_DIM + n] = v;
            }
        }
    }
}

// ---------------- pass B: out[token] += wt * (act @ w2[e] + b2[e]) -------
// grid: x = D/128 (8), y = E*32
__global__ void expert_gemm2(const float* __restrict__ w2,
                             const float* __restrict__ b2,
                             float* __restrict__ out) {
    const int BM = 128, BN = 128, BK = 8;
    int gt = blockIdx.y;
    int e = gt >> 5;
    int m0 = (gt & 31) * BM;
    int cnt = g_counts[e];
    if (m0 >= cnt) return;
    int off = g_offsets[e];
    int n0 = blockIdx.x * BN;
    const float* B = w2 + (size_t)e * F_DIM * D_DIM;

    __shared__ float As[BK][BM];
    __shared__ float Bs[BK][BN];
    int tid = threadIdx.x;
    int arow = tid >> 1, acol = (tid & 1) * 4;
    int brow = tid >> 5, bcol = (tid & 31) * 4;
    int tx = tid % 16, ty = tid / 16;

    bool avalid = (m0 + arow) < cnt;
    size_t arowg = (size_t)(avalid ? (off + m0 + arow) : 0);
    const float* aptr = g_act + arowg * F_DIM + acol;
    const float* bptr = B + (size_t)brow * D_DIM + n0 + bcol;

    float acc[8][8];
    #pragma unroll
    for (int i = 0; i < 8; i++)
        #pragma unroll
        for (int j = 0; j < 8; j++) acc[i][j] = 0.f;

    for (int k0 = 0; k0 < F_DIM; k0 += BK) {
        float4 av = *(const float4*)(aptr + k0);
        As[acol + 0][arow] = av.x;
        As[acol + 1][arow] = av.y;
        As[acol + 2][arow] = av.z;
        As[acol + 3][arow] = av.w;
        float4 bv = *(const float4*)(bptr + (size_t)k0 * D_DIM);
        *(float4*)&Bs[brow][bcol] = bv;
        __syncthreads();
        #pragma unroll
        for (int k = 0; k < BK; k++) {
            float ra[8], rb[8];
            #pragma unroll
            for (int i = 0; i < 8; i++) ra[i] = As[k][ty * 8 + i];
            #pragma unroll
            for (int j = 0; j < 8; j++) rb[j] = Bs[k][tx * 8 + j];
            #pragma unroll
            for (int i = 0; i < 8; i++)
                #pragma unroll
                for (int j = 0; j < 8; j++)
                    acc[i][j] = fmaf(ra[i], rb[j], acc[i][j]);
        }
        __syncthreads();
    }

    #pragma unroll
    for (int i = 0; i < 8; i++) {
        int r = ty * 8 + i;
        if (m0 + r < cnt) {
            int pi = off + m0 + r;
            int tok = g_pair_token[pi];
            float wt = g_pair_w[pi];
            #pragma unroll
            for (int j = 0; j < 8; j++) {
                int n = n0 + tx * 8 + j;
                float v = wt * (acc[i][j] + b2[e * D_DIM + n]);
                atomicAdd(&out[(size_t)tok * D_DIM + n], v);
            }
        }
    }
}

// ---------------- launch ----------------
extern "C" void kernel_launch(void* const* d_in, const int* in_sizes, int n_in,
                              void* d_out, int out_size) {
    const float* h   = (const float*)d_in[0];
    const float* gw1 = (const float*)d_in[1];
    const float* gb1 = (const float*)d_in[2];
    const float* gw2 = (const float*)d_in[3];
    const float* gb2 = (const float*)d_in[4];
    const float* gw3 = (const float*)d_in[5];
    const float* w1  = (const float*)d_in[6];
    const float* b1  = (const float*)d_in[7];
    const float* w2  = (const float*)d_in[8];
    const float* b2  = (const float*)d_in[9];
    (void)in_sizes; (void)n_in;

    float* out = (float*)d_out;                       // [T, D]
    float* out_logits = out + (size_t)T_TOK * D_DIM;  // [T, E] follows
    (void)out_size;

    void *p_g1 = nullptr, *p_g2 = nullptr;
    cudaGetSymbolAddress(&p_g1, g_g1);
    cudaGetSymbolAddress(&p_g2, g_g2);
    float* g1 = (float*)p_g1;
    float* g2 = (float*)p_g2;

    // zero out region [T*D] (float4 granularity)
    {
        int n4 = T_TOK * D_DIM / 4;
        zero_out_kernel<<<(n4 + 255) / 256, 256>>>(out, n4);
    }
    // router layer 1: [4096,1024]x[1024,256]
    gemm_bias_relu<<<dim3(G1_N / 128, T_TOK / 128), 256>>>(h, gw1, gb1, g1, T_TOK, G1_N, D_DIM);
    // router layer 2: [4096,256]x[256,64]  (BN=128 tile with N-guard)
    gemm_bias_relu<<<dim3(1, T_TOK / 128), 256>>>(g1, gw2, gb2, g2, T_TOK, G2_N, G1_N);
    // router logits + top-2 + weights
    router_final<<<T_TOK / 128, 128>>>(gw3, out_logits);
    // deterministic pair lists
    build_pairs<<<1, 256>>>();
    // pass A: act = gelu(gather(h) @ w1 + b1)
    expert_gemm1<<<dim3(F_DIM / 128, E_NUM * 32), 256>>>(h, w1, b1);
    // pass B: out += wt * (act @ w2 + b2)
    expert_gemm2<<<dim3(D_DIM / 128, E_NUM * 32), 256>>>(w2, b2, out);
}

// round 4
// speedup vs baseline: 1.9942x; 1.9942x over previous
#include <cuda_runtime.h>
#include <math.h>
#include <stdint.h>

// ---------------- problem constants ----------------
#define T_TOK 4096
#define D_DIM 1024
#define E_NUM 8
#define F_DIM 4096
#define G1_N  256
#define G2_N  64
#define MAXPAIRS (T_TOK * 2)   // top-2 => exactly 2*T pairs

// ---------------- device scratch (no allocs allowed) ----------------
__device__ float g_g1[T_TOK * G1_N];              // 4 MB
__device__ float g_g2[T_TOK * G2_N];              // 1 MB
__device__ float g_act[(size_t)MAXPAIRS * F_DIM]; // 134 MB intermediate activations
__device__ int   g_topi[T_TOK * 2];
__device__ float g_topw[T_TOK * 2];
__device__ int   g_pair_token[MAXPAIRS];
__device__ float g_pair_w[MAXPAIRS];
__device__ int   g_counts[E_NUM];
__device__ int   g_offsets[E_NUM];

// ---------------- helpers ----------------
__device__ __forceinline__ float gelu_tanh(float x) {
    float x3 = x * x * x;
    float u = 0.7978845608028654f * (x + 0.044715f * x3);
    return 0.5f * x * (1.0f + tanhf(u));
}

__device__ __forceinline__ unsigned f2tf32(float x) {
    unsigned r;
    asm("cvt.rna.tf32.f32 %0, %1;" : "=r"(r) : "f"(x));
    return r;
}

__device__ __forceinline__ void mma_tf32(float* d, const unsigned* a, const unsigned* b) {
    asm volatile(
        "mma.sync.aligned.m16n8k8.row.col.f32.tf32.tf32.f32 "
        "{%0,%1,%2,%3}, {%4,%5,%6,%7}, {%8,%9}, {%0,%1,%2,%3};\n"
        : "+f"(d[0]), "+f"(d[1]), "+f"(d[2]), "+f"(d[3])
        : "r"(a[0]), "r"(a[1]), "r"(a[2]), "r"(a[3]), "r"(b[0]), "r"(b[1]));
}

// ---------------- zero the dense output region ----------------
__global__ void zero_out_kernel(float* __restrict__ out, int n4) {
    int i = blockIdx.x * blockDim.x + threadIdx.x;
    if (i < n4) {
        ((float4*)out)[i] = make_float4(0.f, 0.f, 0.f, 0.f);
    }
}

// ---------------- router: exact fp32 (top-2 selection is precision-sensitive)
// C[M,N] = relu(A[M,K] @ B[K,N] + bias[N]).  M % 128 == 0, K % 8 == 0.
__global__ void gemm_bias_relu(const float* __restrict__ A,
                               const float* __restrict__ B,
                               const float* __restrict__ bias,
                               float* __restrict__ C,
                               int M, int N, int K) {
    const int BM = 128, BN = 128, BK = 8;
    __shared__ float As[BK][BM];
    __shared__ float Bs[BK][BN];
    int tid = threadIdx.x;
    int m0 = blockIdx.y * BM, n0 = blockIdx.x * BN;
    int tx = tid % 16, ty = tid / 16;
    int arow = tid >> 1, acol = (tid & 1) * 4;
    int brow = tid >> 5, bcol = (tid & 31) * 4;
    float acc[8][8];
    #pragma unroll
    for (int i = 0; i < 8; i++)
        #pragma unroll
        for (int j = 0; j < 8; j++) acc[i][j] = 0.f;

    const float* aptr = A + (size_t)(m0 + arow) * K + acol;
    for (int k0 = 0; k0 < K; k0 += BK) {
        float4 av = *(const float4*)(aptr + k0);
        As[acol + 0][arow] = av.x;
        As[acol + 1][arow] = av.y;
        As[acol + 2][arow] = av.z;
        As[acol + 3][arow] = av.w;
        float4 bv = make_float4(0.f, 0.f, 0.f, 0.f);
        if (n0 + bcol < N)
            bv = *(const float4*)(B + (size_t)(k0 + brow) * N + n0 + bcol);
        *(float4*)&Bs[brow][bcol] = bv;
        __syncthreads();
        #pragma unroll
        for (int k = 0; k < BK; k++) {
            float ra[8], rb[8];
            #pragma unroll
            for (int i = 0; i < 8; i++) ra[i] = As[k][ty * 8 + i];
            #pragma unroll
            for (int j = 0; j < 8; j++) rb[j] = Bs[k][tx * 8 + j];
            #pragma unroll
            for (int i = 0; i < 8; i++)
                #pragma unroll
                for (int j = 0; j < 8; j++)
                    acc[i][j] = fmaf(ra[i], rb[j], acc[i][j]);
        }
        __syncthreads();
    }
    #pragma unroll
    for (int i = 0; i < 8; i++) {
        int m = m0 + ty * 8 + i;
        #pragma unroll
        for (int j = 0; j < 8; j++) {
            int n = n0 + tx * 8 + j;
            if (n < N) {
                float v = acc[i][j] + bias[n];
                C[(size_t)m * N + n] = fmaxf(v, 0.f);
            }
        }
    }
}

// ---------------- router final: logits, top-2, normalized weights --------
__global__ void router_final(const float* __restrict__ gw3,
                             float* __restrict__ out_logits) {
    int t = blockIdx.x * blockDim.x + threadIdx.x;
    if (t >= T_TOK) return;
    float l[E_NUM];
    #pragma unroll
    for (int e = 0; e < E_NUM; e++) l[e] = 0.f;
    const float* g = g_g2 + (size_t)t * G2_N;
    for (int k = 0; k < G2_N; k++) {
        float gv = g[k];
        #pragma unroll
        for (int e = 0; e < E_NUM; e++)
            l[e] = fmaf(gv, gw3[k * E_NUM + e], l[e]);
    }
    #pragma unroll
    for (int e = 0; e < E_NUM; e++) out_logits[(size_t)t * E_NUM + e] = l[e];
    int i0 = 0; float v0 = l[0];
    #pragma unroll
    for (int e = 1; e < E_NUM; e++) { if (l[e] > v0) { v0 = l[e]; i0 = e; } }
    int i1 = -1; float v1 = -3.4e38f;
    #pragma unroll
    for (int e = 0; e < E_NUM; e++) { if (e != i0 && l[e] > v1) { v1 = l[e]; i1 = e; } }
    float e1 = expf(v1 - v0);
    float inv = 1.f / (1.f + e1);
    g_topi[2 * t] = i0;  g_topi[2 * t + 1] = i1;
    g_topw[2 * t] = inv; g_topw[2 * t + 1] = e1 * inv;
}

// ---------------- deterministic per-expert pair lists (counting sort) ----
__global__ void build_pairs() {
    __shared__ int s_cnt[E_NUM];
    __shared__ int s_off[E_NUM];
    int tid = threadIdx.x, wid = tid >> 5, lane = tid & 31;
    if (wid < E_NUM) {
        int e = wid, cnt = 0;
        for (int base = 0; base < T_TOK; base += 32) {
            int t = base + lane;
            bool c = (g_topi[2 * t] == e) || (g_topi[2 * t + 1] == e);
            unsigned b = __ballot_sync(0xffffffffu, c);
            cnt += __popc(b);
        }
        if (lane == 0) s_cnt[e] = cnt;
    }
    __syncthreads();
    if (tid == 0) {
        int off = 0;
        for (int e = 0; e < E_NUM; e++) {
            s_off[e] = off; g_offsets[e] = off; g_counts[e] = s_cnt[e];
            off += s_cnt[e];
        }
    }
    __syncthreads();
    if (wid < E_NUM) {
        int e = wid, pos = s_off[e];
        for (int base = 0; base < T_TOK; base += 32) {
            int t = base + lane;
            bool c0 = (g_topi[2 * t] == e);
            bool c  = c0 || (g_topi[2 * t + 1] == e);
            unsigned b = __ballot_sync(0xffffffffu, c);
            int idx = pos + __popc(b & ((1u << lane) - 1u));
            if (c) {
                g_pair_token[idx] = t;
                g_pair_w[idx] = c0 ? g_topw[2 * t] : g_topw[2 * t + 1];
            }
            pos += __popc(b);
        }
    }
}

// ======================================================================
// tf32 tensor-core expert GEMMs
// CTA tile 128x128x16, 256 threads = 8 warps (2 m x 4 n), warp tile 64x32.
// Double-buffered smem, +8 padding => conflict-free LDS fragments.
// ======================================================================
#define SMP 136   // 128 + 8 padding

struct SmemGemm {
    unsigned As[2][16][SMP];
    unsigned Bs[2][16][SMP];
};

// compute one BK=16 k-tile from smem buffer buf
__device__ __forceinline__ void mma_ktile(const unsigned (*As)[SMP],
                                          const unsigned (*Bs)[SMP],
                                          int warp_m, int warp_n, int lane,
                                          float acc[4][4][4]) {
    int r = lane >> 2, c = lane & 3;
    #pragma unroll
    for (int kk = 0; kk < 16; kk += 8) {
        unsigned a[4][4], b[4][2];
        #pragma unroll
        for (int im = 0; im < 4; im++) {
            int m = warp_m * 64 + im * 16 + r;
            a[im][0] = As[kk + c][m];
            a[im][1] = As[kk + c][m + 8];
            a[im][2] = As[kk + c + 4][m];
            a[im][3] = As[kk + c + 4][m + 8];
        }
        #pragma unroll
        for (int jn = 0; jn < 4; jn++) {
            int n = warp_n * 32 + jn * 8 + r;
            b[jn][0] = Bs[kk + c][n];
            b[jn][1] = Bs[kk + c + 4][n];
        }
        #pragma unroll
        for (int im = 0; im < 4; im++)
            #pragma unroll
            for (int jn = 0; jn < 4; jn++)
                mma_tf32(acc[im][jn], a[im], b[jn]);
    }
}

__device__ __forceinline__ void store_a_tile(unsigned (*As)[SMP], int ak, int am,
                                             float4 v0, float4 v1) {
    As[ak + 0][am] = f2tf32(v0.x);
    As[ak + 1][am] = f2tf32(v0.y);
    As[ak + 2][am] = f2tf32(v0.z);
    As[ak + 3][am] = f2tf32(v0.w);
    As[ak + 4][am] = f2tf32(v1.x);
    As[ak + 5][am] = f2tf32(v1.y);
    As[ak + 6][am] = f2tf32(v1.z);
    As[ak + 7][am] = f2tf32(v1.w);
}

__device__ __forceinline__ void store_b_tile(unsigned (*Bs)[SMP], int bk, int bn,
                                             float4 v0, float4 v1) {
    uint4 u0 = make_uint4(f2tf32(v0.x), f2tf32(v0.y), f2tf32(v0.z), f2tf32(v0.w));
    uint4 u1 = make_uint4(f2tf32(v1.x), f2tf32(v1.y), f2tf32(v1.z), f2tf32(v1.w));
    *(uint4*)&Bs[bk][bn + 0] = u0;
    *(uint4*)&Bs[bk][bn + 4] = u1;
}

// ---------------- pass A: act = gelu(gather(h) @ w1[e] + b1[e]) ----------
// grid: x = F/128 (32), y = E*32
__global__ void __launch_bounds__(256)
expert_gemm1_tc(const float* __restrict__ h,
                const float* __restrict__ w1,
                const float* __restrict__ b1) {
    __shared__ SmemGemm sm;
    int gt = blockIdx.y;
    int e = gt >> 5;
    int m0 = (gt & 31) * 128;
    int cnt = g_counts[e];
    if (m0 >= cnt) return;
    int off = g_offsets[e];
    int n0 = blockIdx.x * 128;
    const float* B = w1 + (size_t)e * D_DIM * F_DIM;

    int tid = threadIdx.x, lane = tid & 31, wid = tid >> 5;
    int warp_m = wid & 1, warp_n = wid >> 1;

    // A load mapping: row = tid&127 (token-gathered), k-half = tid>>7
    int am = tid & 127;
    int ak = (tid >> 7) * 8;
    int tokenA = (m0 + am < cnt) ? g_pair_token[off + m0 + am] : g_pair_token[off];
    const float* aptr = h + (size_t)tokenA * D_DIM + ak;
    // B load mapping: row = tid>>4, cols = (tid&15)*8
    int bk = tid >> 4;
    int bn = (tid & 15) * 8;
    const float* bptr = B + (size_t)bk * F_DIM + n0 + bn;

    float acc[4][4][4];
    #pragma unroll
    for (int im = 0; im < 4; im++)
        #pragma unroll
        for (int jn = 0; jn < 4; jn++)
            #pragma unroll
            for (int q = 0; q < 4; q++) acc[im][jn][q] = 0.f;

    const int NT = D_DIM / 16;
    // prologue: tile 0
    float4 va0 = *(const float4*)(aptr);
    float4 va1 = *(const float4*)(aptr + 4);
    float4 vb0 = *(const float4*)(bptr);
    float4 vb1 = *(const float4*)(bptr + 4);
    store_a_tile(sm.As[0], ak, am, va0, va1);
    store_b_tile(sm.Bs[0], bk, bn, vb0, vb1);
    __syncthreads();

    for (int kt = 0; kt < NT; kt++) {
        int cur = kt & 1;
        if (kt + 1 < NT) {
            int k0 = (kt + 1) * 16;
            va0 = *(const float4*)(aptr + k0);
            va1 = *(const float4*)(aptr + k0 + 4);
            vb0 = *(const float4*)(bptr + (size_t)k0 * F_DIM);
            vb1 = *(const float4*)(bptr + (size_t)k0 * F_DIM + 4);
        }
        mma_ktile(sm.As[cur], sm.Bs[cur], warp_m, warp_n, lane, acc);
        if (kt + 1 < NT) {
            store_a_tile(sm.As[cur ^ 1], ak, am, va0, va1);
            store_b_tile(sm.Bs[cur ^ 1], bk, bn, vb0, vb1);
        }
        __syncthreads();
    }

    // epilogue: gelu(acc + bias) -> g_act
    int r = lane >> 2, c2 = (lane & 3) * 2;
    #pragma unroll
    for (int im = 0; im < 4; im++) {
        #pragma unroll
        for (int half = 0; half < 2; half++) {
            int mloc = warp_m * 64 + im * 16 + r + half * 8;
            if (m0 + mloc < cnt) {
                size_t pi = (size_t)(off + m0 + mloc);
                #pragma unroll
                for (int jn = 0; jn < 4; jn++) {
                    int n = n0 + warp_n * 32 + jn * 8 + c2;
                    float vx = acc[im][jn][half * 2 + 0] + b1[e * F_DIM + n + 0];
                    float vy = acc[im][jn][half * 2 + 1] + b1[e * F_DIM + n + 1];
                    float2 v = make_float2(gelu_tanh(vx), gelu_tanh(vy));
                    *(float2*)&g_act[pi * F_DIM + n] = v;
                }
            }
        }
    }
}

// ---------------- pass B: out[token] += wt * (act @ w2[e] + b2[e]) -------
// grid: x = D/128 (8), y = E*32
__global__ void __launch_bounds__(256)
expert_gemm2_tc(const float* __restrict__ w2,
                const float* __restrict__ b2,
                float* __restrict__ out) {
    __shared__ SmemGemm sm;
    int gt = blockIdx.y;
    int e = gt >> 5;
    int m0 = (gt & 31) * 128;
    int cnt = g_counts[e];
    if (m0 >= cnt) return;
    int off = g_offsets[e];
    int n0 = blockIdx.x * 128;
    const float* B = w2 + (size_t)e * F_DIM * D_DIM;

    int tid = threadIdx.x, lane = tid & 31, wid = tid >> 5;
    int warp_m = wid & 1, warp_n = wid >> 1;

    int am = tid & 127;
    int ak = (tid >> 7) * 8;
    size_t arow = (size_t)((m0 + am < cnt) ? (off + m0 + am) : off);
    const float* aptr = g_act + arow * F_DIM + ak;
    int bk = tid >> 4;
    int bn = (tid & 15) * 8;
    const float* bptr = B + (size_t)bk * D_DIM + n0 + bn;

    float acc[4][4][4];
    #pragma unroll
    for (int im = 0; im < 4; im++)
        #pragma unroll
        for (int jn = 0; jn < 4; jn++)
            #pragma unroll
            for (int q = 0; q < 4; q++) acc[im][jn][q] = 0.f;

    const int NT = F_DIM / 16;
    float4 va0 = *(const float4*)(aptr);
    float4 va1 = *(const float4*)(aptr + 4);
    float4 vb0 = *(const float4*)(bptr);
    float4 vb1 = *(const float4*)(bptr + 4);
    store_a_tile(sm.As[0], ak, am, va0, va1);
    store_b_tile(sm.Bs[0], bk, bn, vb0, vb1);
    __syncthreads();

    for (int kt = 0; kt < NT; kt++) {
        int cur = kt & 1;
        if (kt + 1 < NT) {
            int k0 = (kt + 1) * 16;
            va0 = *(const float4*)(aptr + k0);
            va1 = *(const float4*)(aptr + k0 + 4);
            vb0 = *(const float4*)(bptr + (size_t)k0 * D_DIM);
            vb1 = *(const float4*)(bptr + (size_t)k0 * D_DIM + 4);
        }
        mma_ktile(sm.As[cur], sm.Bs[cur], warp_m, warp_n, lane, acc);
        if (kt + 1 < NT) {
            store_a_tile(sm.As[cur ^ 1], ak, am, va0, va1);
            store_b_tile(sm.Bs[cur ^ 1], bk, bn, vb0, vb1);
        }
        __syncthreads();
    }

    // epilogue: out[token] += wt * (acc + b2)
    int r = lane >> 2, c2 = (lane & 3) * 2;
    #pragma unroll
    for (int im = 0; im < 4; im++) {
        #pragma unroll
        for (int half = 0; half < 2; half++) {
            int mloc = warp_m * 64 + im * 16 + r + half * 8;
            if (m0 + mloc < cnt) {
                int pi = off + m0 + mloc;
                int tok = g_pair_token[pi];
                float wt = g_pair_w[pi];
                #pragma unroll
                for (int jn = 0; jn < 4; jn++) {
                    int n = n0 + warp_n * 32 + jn * 8 + c2;
                    float vx = wt * (acc[im][jn][half * 2 + 0] + b2[e * D_DIM + n + 0]);
                    float vy = wt * (acc[im][jn][half * 2 + 1] + b2[e * D_DIM + n + 1]);
                    atomicAdd(&out[(size_t)tok * D_DIM + n + 0], vx);
                    atomicAdd(&out[(size_t)tok * D_DIM + n + 1], vy);
                }
            }
        }
    }
}

// ---------------- launch ----------------
extern "C" void kernel_launch(void* const* d_in, const int* in_sizes, int n_in,
                              void* d_out, int out_size) {
    const float* h   = (const float*)d_in[0];
    const float* gw1 = (const float*)d_in[1];
    const float* gb1 = (const float*)d_in[2];
    const float* gw2 = (const float*)d_in[3];
    const float* gb2 = (const float*)d_in[4];
    const float* gw3 = (const float*)d_in[5];
    const float* w1  = (const float*)d_in[6];
    const float* b1  = (const float*)d_in[7];
    const float* w2  = (const float*)d_in[8];
    const float* b2  = (const float*)d_in[9];
    (void)in_sizes; (void)n_in;

    float* out = (float*)d_out;                       // [T, D]
    float* out_logits = out + (size_t)T_TOK * D_DIM;  // [T, E] follows
    (void)out_size;

    void *p_g1 = nullptr, *p_g2 = nullptr;
    cudaGetSymbolAddress(&p_g1, g_g1);
    cudaGetSymbolAddress(&p_g2, g_g2);
    float* g1 = (float*)p_g1;
    float* g2 = (float*)p_g2;

    {
        int n4 = T_TOK * D_DIM / 4;
        zero_out_kernel<<<(n4 + 255) / 256, 256>>>(out, n4);
    }
    // router (exact fp32)
    gemm_bias_relu<<<dim3(G1_N / 128, T_TOK / 128), 256>>>(h, gw1, gb1, g1, T_TOK, G1_N, D_DIM);
    gemm_bias_relu<<<dim3(1, T_TOK / 128), 256>>>(g1, gw2, gb2, g2, T_TOK, G2_N, G1_N);
    router_final<<<T_TOK / 128, 128>>>(gw3, out_logits);
    build_pairs<<<1, 256>>>();
    // experts (tf32 tensor cores)
    expert_gemm1_tc<<<dim3(F_DIM / 128, E_NUM * 32), 256>>>(h, w1, b1);
    expert_gemm2_tc<<<dim3(D_DIM / 128, E_NUM * 32), 256>>>(w2, b2, out);
}

// round 7
// speedup vs baseline: 3.5994x; 1.8049x over previous
#include <cuda_runtime.h>
#include <cuda_fp16.h>
#include <math.h>
#include <stdint.h>

// ---------------- problem constants ----------------
#define T_TOK 4096
#define D_DIM 1024
#define E_NUM 8
#define F_DIM 4096
#define G1_N  256
#define G2_N  64
#define MAXPAIRS (T_TOK * 2)

// ---------------- device scratch (no allocs allowed) ----------------
__device__ float  g_g1[T_TOK * G1_N];
__device__ float  g_g2[T_TOK * G2_N];
__device__ __half g_acth[(size_t)MAXPAIRS * F_DIM];         // 64 MB fp16 activations
__device__ __half g_hh[(size_t)T_TOK * D_DIM];              // 8 MB fp16 hidden states
__device__ __half g_w1t[(size_t)E_NUM * F_DIM * D_DIM];     // 64 MB [e][F][D] (n-major, k-contig)
__device__ __half g_w2t[(size_t)E_NUM * D_DIM * F_DIM];     // 64 MB [e][D][F]
__device__ int    g_topi[T_TOK * 2];
__device__ float  g_topw[T_TOK * 2];
__device__ int    g_pair_token[MAXPAIRS];
__device__ float  g_pair_w[MAXPAIRS];
__device__ int    g_counts[E_NUM];
__device__ int    g_offsets[E_NUM];

// ---------------- helpers ----------------
__device__ __forceinline__ float gelu_tanh(float x) {
    float x3 = x * x * x;
    float u = 0.7978845608028654f * (x + 0.044715f * x3);
    return 0.5f * x * (1.0f + tanhf(u));
}

__device__ __forceinline__ uint32_t smem_u32(const void* p) {
    uint32_t a;
    asm("{ .reg .u64 t; cvta.to.shared.u64 t, %1; cvt.u32.u64 %0, t; }" : "=r"(a) : "l"(p));
    return a;
}

__device__ __forceinline__ void cpasync16(uint32_t s, const void* g) {
    asm volatile("cp.async.cg.shared.global [%0], [%1], 16;" :: "r"(s), "l"(g));
}
#define CP_COMMIT() asm volatile("cp.async.commit_group;" ::: "memory")
#define CP_WAIT0()  asm volatile("cp.async.wait_group 0;" ::: "memory")
#define CP_WAIT1()  asm volatile("cp.async.wait_group 1;" ::: "memory")

__device__ __forceinline__ void mma16816(float* d, const uint32_t* a, const uint32_t* b) {
    asm volatile(
        "mma.sync.aligned.m16n8k16.row.col.f32.f16.f16.f32 "
        "{%0,%1,%2,%3}, {%4,%5,%6,%7}, {%8,%9}, {%0,%1,%2,%3};\n"
        : "+f"(d[0]), "+f"(d[1]), "+f"(d[2]), "+f"(d[3])
        : "r"(a[0]), "r"(a[1]), "r"(a[2]), "r"(a[3]), "r"(b[0]), "r"(b[1]));
}

// ---------------- zero output ----------------
__global__ void zero_out_kernel(float* __restrict__ out, int n4) {
    int i = blockIdx.x * blockDim.x + threadIdx.x;
    if (i < n4) ((float4*)out)[i] = make_float4(0.f, 0.f, 0.f, 0.f);
}

// ---------------- one-time fp32 -> fp16 conversions ----------------
__global__ void f2h_kernel(const float* __restrict__ in, __half* __restrict__ out, int n4) {
    int i = blockIdx.x * blockDim.x + threadIdx.x;
    if (i < n4) {
        float4 v = ((const float4*)in)[i];
        __half2 a = __floats2half2_rn(v.x, v.y);
        __half2 b = __floats2half2_rn(v.z, v.w);
        ((__half2*)out)[2 * i + 0] = a;
        ((__half2*)out)[2 * i + 1] = b;
    }
}

// batched transpose: in [R][C] fp32 row-major  ->  out [C][R] fp16 (z = batch)
__global__ void transpose_f2h(const float* __restrict__ in, __half* __restrict__ out,
                              int R, int C) {
    __shared__ float t[32][33];
    size_t base = (size_t)blockIdx.z * R * C;
    int x = blockIdx.x * 32 + threadIdx.x;  // input col
    int y = blockIdx.y * 32 + threadIdx.y;  // input row
    #pragma unroll
    for (int j = 0; j < 32; j += 8)
        t[threadIdx.y + j][threadIdx.x] = in[base + (size_t)(y + j) * C + x];
    __syncthreads();
    int ox = blockIdx.y * 32 + threadIdx.x; // output col (= input row)
    int oy = blockIdx.x * 32 + threadIdx.y; // output row (= input col)
    #pragma unroll
    for (int j = 0; j < 32; j += 8)
        out[base + (size_t)(oy + j) * R + ox] = __float2half_rn(t[threadIdx.x][threadIdx.y + j]);
}

// ---------------- router: exact fp32 ----------------
__global__ void gemm_bias_relu(const float* __restrict__ A, const float* __restrict__ B,
                               const float* __restrict__ bias, float* __restrict__ C,
                               int M, int N, int K) {
    const int BKr = 8;
    __shared__ float As[BKr][128];
    __shared__ float Bs[BKr][128];
    int tid = threadIdx.x;
    int m0 = blockIdx.y * 128, n0 = blockIdx.x * 128;
    int tx = tid % 16, ty = tid / 16;
    int arow = tid >> 1, acol = (tid & 1) * 4;
    int brow = tid >> 5, bcol = (tid & 31) * 4;
    float acc[8][8];
    #pragma unroll
    for (int i = 0; i < 8; i++)
        #pragma unroll
        for (int j = 0; j < 8; j++) acc[i][j] = 0.f;
    const float* aptr = A + (size_t)(m0 + arow) * K + acol;
    for (int k0 = 0; k0 < K; k0 += BKr) {
        float4 av = *(const float4*)(aptr + k0);
        As[acol + 0][arow] = av.x; As[acol + 1][arow] = av.y;
        As[acol + 2][arow] = av.z; As[acol + 3][arow] = av.w;
        float4 bv = make_float4(0.f, 0.f, 0.f, 0.f);
        if (n0 + bcol < N) bv = *(const float4*)(B + (size_t)(k0 + brow) * N + n0 + bcol);
        *(float4*)&Bs[brow][bcol] = bv;
        __syncthreads();
        #pragma unroll
        for (int k = 0; k < BKr; k++) {
            float ra[8], rb[8];
            #pragma unroll
            for (int i = 0; i < 8; i++) ra[i] = As[k][ty * 8 + i];
            #pragma unroll
            for (int j = 0; j < 8; j++) rb[j] = Bs[k][tx * 8 + j];
            #pragma unroll
            for (int i = 0; i < 8; i++)
                #pragma unroll
                for (int j = 0; j < 8; j++) acc[i][j] = fmaf(ra[i], rb[j], acc[i][j]);
        }
        __syncthreads();
    }
    #pragma unroll
    for (int i = 0; i < 8; i++) {
        int m = m0 + ty * 8 + i;
        #pragma unroll
        for (int j = 0; j < 8; j++) {
            int n = n0 + tx * 8 + j;
            if (n < N) C[(size_t)m * N + n] = fmaxf(acc[i][j] + bias[n], 0.f);
        }
    }
}

__global__ void router_final(const float* __restrict__ gw3, float* __restrict__ out_logits) {
    int t = blockIdx.x * blockDim.x + threadIdx.x;
    if (t >= T_TOK) return;
    float l[E_NUM];
    #pragma unroll
    for (int e = 0; e < E_NUM; e++) l[e] = 0.f;
    const float* g = g_g2 + (size_t)t * G2_N;
    for (int k = 0; k < G2_N; k++) {
        float gv = g[k];
        #pragma unroll
        for (int e = 0; e < E_NUM; e++) l[e] = fmaf(gv, gw3[k * E_NUM + e], l[e]);
    }
    #pragma unroll
    for (int e = 0; e < E_NUM; e++) out_logits[(size_t)t * E_NUM + e] = l[e];
    int i0 = 0; float v0 = l[0];
    #pragma unroll
    for (int e = 1; e < E_NUM; e++) { if (l[e] > v0) { v0 = l[e]; i0 = e; } }
    int i1 = -1; float v1 = -3.4e38f;
    #pragma unroll
    for (int e = 0; e < E_NUM; e++) { if (e != i0 && l[e] > v1) { v1 = l[e]; i1 = e; } }
    float e1 = expf(v1 - v0);
    float inv = 1.f / (1.f + e1);
    g_topi[2 * t] = i0;  g_topi[2 * t + 1] = i1;
    g_topw[2 * t] = inv; g_topw[2 * t + 1] = e1 * inv;
}

__global__ void build_pairs() {
    __shared__ int s_cnt[E_NUM];
    __shared__ int s_off[E_NUM];
    int tid = threadIdx.x, wid = tid >> 5, lane = tid & 31;
    if (wid < E_NUM) {
        int e = wid, cnt = 0;
        for (int base = 0; base < T_TOK; base += 32) {
            int t = base + lane;
            bool c = (g_topi[2 * t] == e) || (g_topi[2 * t + 1] == e);
            cnt += __popc(__ballot_sync(0xffffffffu, c));
        }
        if (lane == 0) s_cnt[e] = cnt;
    }
    __syncthreads();
    if (tid == 0) {
        int off = 0;
        for (int e = 0; e < E_NUM; e++) {
            s_off[e] = off; g_offsets[e] = off; g_counts[e] = s_cnt[e];
            off += s_cnt[e];
        }
    }
    __syncthreads();
    if (wid < E_NUM) {
        int e = wid, pos = s_off[e];
        for (int base = 0; base < T_TOK; base += 32) {
            int t = base + lane;
            bool c0 = (g_topi[2 * t] == e);
            bool c  = c0 || (g_topi[2 * t + 1] == e);
            unsigned b = __ballot_sync(0xffffffffu, c);
            int idx = pos + __popc(b & ((1u << lane) - 1u));
            if (c) {
                g_pair_token[idx] = t;
                g_pair_w[idx] = c0 ? g_topw[2 * t] : g_topw[2 * t + 1];
            }
            pos += __popc(b);
        }
    }
}

// ======================================================================
// fp16 mma.sync expert GEMMs. CTA tile 128x128, BK=32, 8 warps (2m x 4n),
// warp tile 64x32, m16n8k16. Operands fp16 k-contiguous -> pure cp.async.
// Smem row pad to 40 halves (80B): conflict-free fragment LDS.
// ======================================================================
#define BK   32
#define KPAD 40

struct SmT {
    __half A[2][128][KPAD];   // 20 KB
    __half B[2][128][KPAD];   // 20 KB
};

// ---------------- pass A: act = gelu(gather(hh) @ w1t[e]^T + b1[e]) ------
__global__ void __launch_bounds__(256, 2)
expert_g1_fp16(const __half* __restrict__ w1t, const float* __restrict__ b1) {
    __shared__ SmT sm;
    int gt = blockIdx.y;
    int e = gt >> 5;
    int m0 = (gt & 31) * 128;
    int cnt = g_counts[e];
    if (m0 >= cnt) return;
    int off = g_offsets[e];
    int n0 = blockIdx.x * 128;
    const __half* Bt = w1t + (size_t)e * F_DIM * D_DIM;

    int tid = threadIdx.x, lane = tid & 31, wid = tid >> 5;
    int warp_m = wid & 1, warp_n = wid >> 1;

    // cp.async mapping: 512 16B-chunks per tile (128 rows x 4 chunks); 2 per thread
    int c0 = tid * 2, c1 = tid * 2 + 1;
    int ar0 = c0 >> 2, ac0 = c0 & 3;
    int ar1 = c1 >> 2, ac1 = c1 & 3;
    int p0 = (m0 + ar0 < cnt) ? off + m0 + ar0 : off;
    int p1 = (m0 + ar1 < cnt) ? off + m0 + ar1 : off;
    const __half* asrc0 = g_hh + (size_t)g_pair_token[p0] * D_DIM + ac0 * 8;
    const __half* asrc1 = g_hh + (size_t)g_pair_token[p1] * D_DIM + ac1 * 8;
    const __half* bsrc0 = Bt + (size_t)(n0 + ar0) * D_DIM + ac0 * 8;
    const __half* bsrc1 = Bt + (size_t)(n0 + ar1) * D_DIM + ac1 * 8;

    uint32_t sa = smem_u32(&sm);
    const uint32_t ABUF = 128 * KPAD * 2;
    uint32_t ad0 = sa + (uint32_t)(ar0 * KPAD + ac0 * 8) * 2;
    uint32_t ad1 = sa + (uint32_t)(ar1 * KPAD + ac1 * 8) * 2;
    uint32_t bd0 = sa + 2 * ABUF + (uint32_t)(ar0 * KPAD + ac0 * 8) * 2;
    uint32_t bd1 = sa + 2 * ABUF + (uint32_t)(ar1 * KPAD + ac1 * 8) * 2;

    float acc[4][4][4];
    #pragma unroll
    for (int im = 0; im < 4; im++)
        #pragma unroll
        for (int jn = 0; jn < 4; jn++)
            #pragma unroll
            for (int q = 0; q < 4; q++) acc[im][jn][q] = 0.f;

    const int NT = D_DIM / BK;
    // prologue
    cpasync16(ad0, asrc0); cpasync16(ad1, asrc1);
    cpasync16(bd0, bsrc0); cpasync16(bd1, bsrc1);
    CP_COMMIT();

    int g = lane >> 2, t2 = (lane & 3) * 2;
    for (int kt = 0; kt < NT; kt++) {
        int buf = kt & 1;
        if (kt + 1 < NT) {
            int kb = (kt + 1) * BK;
            uint32_t bo = (uint32_t)(buf ^ 1) * ABUF;
            cpasync16(ad0 + bo, asrc0 + kb); cpasync16(ad1 + bo, asrc1 + kb);
            cpasync16(bd0 + bo, bsrc0 + kb); cpasync16(bd1 + bo, bsrc1 + kb);
            CP_COMMIT();
            CP_WAIT1();
        } else {
            CP_WAIT0();
        }
        __syncthreads();
        const __half (*As)[KPAD] = sm.A[buf];
        const __half (*Bs)[KPAD] = sm.B[buf];
        #pragma unroll
        for (int kk = 0; kk < BK; kk += 16) {
            uint32_t a[4][4], b[4][2];
            #pragma unroll
            for (int im = 0; im < 4; im++) {
                int m = warp_m * 64 + im * 16;
                a[im][0] = *(const uint32_t*)&As[m + g][kk + t2];
                a[im][1] = *(const uint32_t*)&As[m + g + 8][kk + t2];
                a[im][2] = *(const uint32_t*)&As[m + g][kk + t2 + 8];
                a[im][3] = *(const uint32_t*)&As[m + g + 8][kk + t2 + 8];
            }
            #pragma unroll
            for (int jn = 0; jn < 4; jn++) {
                int n = warp_n * 32 + jn * 8 + g;
                b[jn][0] = *(const uint32_t*)&Bs[n][kk + t2];
                b[jn][1] = *(const uint32_t*)&Bs[n][kk + t2 + 8];
            }
            #pragma unroll
            for (int im = 0; im < 4; im++)
                #pragma unroll
                for (int jn = 0; jn < 4; jn++)
                    mma16816(acc[im][jn], a[im], b[jn]);
        }
        __syncthreads();
    }

    // epilogue: gelu(acc + b1) -> g_acth (fp16)
    #pragma unroll
    for (int im = 0; im < 4; im++) {
        #pragma unroll
        for (int half = 0; half < 2; half++) {
            int mloc = warp_m * 64 + im * 16 + g + half * 8;
            if (m0 + mloc < cnt) {
                size_t pi = (size_t)(off + m0 + mloc);
                #pragma unroll
                for (int jn = 0; jn < 4; jn++) {
                    int n = n0 + warp_n * 32 + jn * 8 + t2;
                    float vx = acc[im][jn][half * 2 + 0] + b1[e * F_DIM + n + 0];
                    float vy = acc[im][jn][half * 2 + 1] + b1[e * F_DIM + n + 1];
                    __half2 hv = __floats2half2_rn(gelu_tanh(vx), gelu_tanh(vy));
                    *(__half2*)&g_acth[pi * F_DIM + n] = hv;
                }
            }
        }
    }
}

// ---------------- pass B: out[token] += wt * (acth @ w2t[e]^T + b2[e]) ---
__global__ void __launch_bounds__(256, 2)
expert_g2_fp16(const __half* __restrict__ w2t, const float* __restrict__ b2,
               float* __restrict__ out) {
    __shared__ SmT sm;
    int gt = blockIdx.y;
    int e = gt >> 5;
    int m0 = (gt & 31) * 128;
    int cnt = g_counts[e];
    if (m0 >= cnt) return;
    int off = g_offsets[e];
    int n0 = blockIdx.x * 128;
    const __half* Bt = w2t + (size_t)e * D_DIM * F_DIM;

    int tid = threadIdx.x, lane = tid & 31, wid = tid >> 5;
    int warp_m = wid & 1, warp_n = wid >> 1;

    int c0 = tid * 2, c1 = tid * 2 + 1;
    int ar0 = c0 >> 2, ac0 = c0 & 3;
    int ar1 = c1 >> 2, ac1 = c1 & 3;
    size_t p0 = (size_t)((m0 + ar0 < cnt) ? off + m0 + ar0 : off);
    size_t p1 = (size_t)((m0 + ar1 < cnt) ? off + m0 + ar1 : off);
    const __half* asrc0 = g_acth + p0 * F_DIM + ac0 * 8;
    const __half* asrc1 = g_acth + p1 * F_DIM + ac1 * 8;
    const __half* bsrc0 = Bt + (size_t)(n0 + ar0) * F_DIM + ac0 * 8;
    const __half* bsrc1 = Bt + (size_t)(n0 + ar1) * F_DIM + ac1 * 8;

    uint32_t sa = smem_u32(&sm);
    const uint32_t ABUF = 128 * KPAD * 2;
    uint32_t ad0 = sa + (uint32_t)(ar0 * KPAD + ac0 * 8) * 2;
    uint32_t ad1 = sa + (uint32_t)(ar1 * KPAD + ac1 * 8) * 2;
    uint32_t bd0 = sa + 2 * ABUF + (uint32_t)(ar0 * KPAD + ac0 * 8) * 2;
    uint32_t bd1 = sa + 2 * ABUF + (uint32_t)(ar1 * KPAD + ac1 * 8) * 2;

    float acc[4][4][4];
    #pragma unroll
    for (int im = 0; im < 4; im++)
        #pragma unroll
        for (int jn = 0; jn < 4; jn++)
            #pragma unroll
            for (int q = 0; q < 4; q++) acc[im][jn][q] = 0.f;

    const int NT = F_DIM / BK;
    cpasync16(ad0, asrc0); cpasync16(ad1, asrc1);
    cpasync16(bd0, bsrc0); cpasync16(bd1, bsrc1);
    CP_COMMIT();

    int g = lane >> 2, t2 = (lane & 3) * 2;
    for (int kt = 0; kt < NT; kt++) {
        int buf = kt & 1;
        if (kt + 1 < NT) {
            int kb = (kt + 1) * BK;
            uint32_t bo = (uint32_t)(buf ^ 1) * ABUF;
            cpasync16(ad0 + bo, asrc0 + kb); cpasync16(ad1 + bo, asrc1 + kb);
            cpasync16(bd0 + bo, bsrc0 + kb); cpasync16(bd1 + bo, bsrc1 + kb);
            CP_COMMIT();
            CP_WAIT1();
        } else {
            CP_WAIT0();
        }
        __syncthreads();
        const __half (*As)[KPAD] = sm.A[buf];
        const __half (*Bs)[KPAD] = sm.B[buf];
        #pragma unroll
        for (int kk = 0; kk < BK; kk += 16) {
            uint32_t a[4][4], b[4][2];
            #pragma unroll
            for (int im = 0; im < 4; im++) {
                int m = warp_m * 64 + im * 16;
                a[im][0] = *(const uint32_t*)&As[m + g][kk + t2];
                a[im][1] = *(const uint32_t*)&As[m + g + 8][kk + t2];
                a[im][2] = *(const uint32_t*)&As[m + g][kk + t2 + 8];
                a[im][3] = *(const uint32_t*)&As[m + g + 8][kk + t2 + 8];
            }
            #pragma unroll
            for (int jn = 0; jn < 4; jn++) {
                int n = warp_n * 32 + jn * 8 + g;
                b[jn][0] = *(const uint32_t*)&Bs[n][kk + t2];
                b[jn][1] = *(const uint32_t*)&Bs[n][kk + t2 + 8];
            }
            #pragma unroll
            for (int im = 0; im < 4; im++)
                #pragma unroll
                for (int jn = 0; jn < 4; jn++)
                    mma16816(acc[im][jn], a[im], b[jn]);
        }
        __syncthreads();
    }

    // epilogue: out[token] += wt * (acc + b2)
    #pragma unroll
    for (int im = 0; im < 4; im++) {
        #pragma unroll
        for (int half = 0; half < 2; half++) {
            int mloc = warp_m * 64 + im * 16 + g + half * 8;
            if (m0 + mloc < cnt) {
                int pi = off + m0 + mloc;
                int tok = g_pair_token[pi];
                float wt = g_pair_w[pi];
                #pragma unroll
                for (int jn = 0; jn < 4; jn++) {
                    int n = n0 + warp_n * 32 + jn * 8 + t2;
                    float vx = wt * (acc[im][jn][half * 2 + 0] + b2[e * D_DIM + n + 0]);
                    float vy = wt * (acc[im][jn][half * 2 + 1] + b2[e * D_DIM + n + 1]);
                    atomicAdd(&out[(size_t)tok * D_DIM + n + 0], vx);
                    atomicAdd(&out[(size_t)tok * D_DIM + n + 1], vy);
                }
            }
        }
    }
}

// ---------------- launch ----------------
extern "C" void kernel_launch(void* const* d_in, const int* in_sizes, int n_in,
                              void* d_out, int out_size) {
    const float* h   = (const float*)d_in[0];
    const float* gw1 = (const float*)d_in[1];
    const float* gb1 = (const float*)d_in[2];
    const float* gw2 = (const float*)d_in[3];
    const float* gb2 = (const float*)d_in[4];
    const float* gw3 = (const float*)d_in[5];
    const float* w1  = (const float*)d_in[6];
    const float* b1  = (const float*)d_in[7];
    const float* w2  = (const float*)d_in[8];
    const float* b2  = (const float*)d_in[9];
    (void)in_sizes; (void)n_in; (void)out_size;

    float* out = (float*)d_out;
    float* out_logits = out + (size_t)T_TOK * D_DIM;

    void *p_g1 = nullptr, *p_g2 = nullptr, *p_hh = nullptr, *p_w1t = nullptr, *p_w2t = nullptr;
    cudaGetSymbolAddress(&p_g1, g_g1);
    cudaGetSymbolAddress(&p_g2, g_g2);
    cudaGetSymbolAddress(&p_hh, g_hh);
    cudaGetSymbolAddress(&p_w1t, g_w1t);
    cudaGetSymbolAddress(&p_w2t, g_w2t);
    float*  g1  = (float*)p_g1;
    float*  g2  = (float*)p_g2;
    __half* hh  = (__half*)p_hh;
    __half* w1t = (__half*)p_w1t;
    __half* w2t = (__half*)p_w2t;

    // zero dense output
    {
        int n4 = T_TOK * D_DIM / 4;
        zero_out_kernel<<<(n4 + 255) / 256, 256>>>(out, n4);
    }
    // one-time conversions / transposes to fp16
    {
        int n4 = T_TOK * D_DIM / 4;
        f2h_kernel<<<(n4 + 255) / 256, 256>>>(h, hh, n4);
        // w1 [E][D][F] -> w1t [E][F][D]
        transpose_f2h<<<dim3(F_DIM / 32, D_DIM / 32, E_NUM), dim3(32, 8)>>>(w1, w1t, D_DIM, F_DIM);
        // w2 [E][F][D] -> w2t [E][D][F]
        transpose_f2h<<<dim3(D_DIM / 32, F_DIM / 32, E_NUM), dim3(32, 8)>>>(w2, w2t, F_DIM, D_DIM);
    }
    // router (exact fp32)
    gemm_bias_relu<<<dim3(G1_N / 128, T_TOK / 128), 256>>>(h, gw1, gb1, g1, T_TOK, G1_N, D_DIM);
    gemm_bias_relu<<<dim3(1, T_TOK / 128), 256>>>(g1, gw2, gb2, g2, T_TOK, G2_N, G1_N);
    router_final<<<T_TOK / 128, 128>>>(gw3, out_logits);
    build_pairs<<<1, 256>>>();
    // experts (fp16 mma.sync m16n8k16 + cp.async)
    expert_g1_fp16<<<dim3(F_DIM / 128, E_NUM * 32), 256>>>(w1t, b1);
    expert_g2_fp16<<<dim3(D_DIM / 128, E_NUM * 32), 256>>>(w2t, b2, out);
}

// round 8
// speedup vs baseline: 4.5495x; 1.2640x over previous
#include <cuda_runtime.h>
#include <cuda_fp16.h>
#include <math.h>
#include <stdint.h>

// ---------------- problem constants ----------------
#define T_TOK 4096
#define D_DIM 1024
#define E_NUM 8
#define F_DIM 4096
#define G1_N  256
#define G2_N  64
#define MAXPAIRS (T_TOK * 2)

// ---------------- device scratch (no allocs allowed) ----------------
__device__ float  g_g1[T_TOK * G1_N];
__device__ float  g_g2[T_TOK * G2_N];
__device__ __half g_acth[(size_t)MAXPAIRS * F_DIM];         // 64 MB fp16 activations
__device__ __half g_hh[(size_t)T_TOK * D_DIM];              // 8 MB fp16 hidden states
__device__ __half g_w1t[(size_t)E_NUM * F_DIM * D_DIM];     // 64 MB [e][F][D]
__device__ __half g_w2t[(size_t)E_NUM * D_DIM * F_DIM];     // 64 MB [e][D][F]
__device__ int    g_topi[T_TOK * 2];
__device__ float  g_topw[T_TOK * 2];
__device__ int    g_pair_token[MAXPAIRS];
__device__ float  g_pair_w[MAXPAIRS];
__device__ int    g_counts[E_NUM];
__device__ int    g_offsets[E_NUM];

// ---------------- helpers ----------------
__device__ __forceinline__ float gelu_tanh(float x) {
    float x3 = x * x * x;
    float u = 0.7978845608028654f * (x + 0.044715f * x3);
    return 0.5f * x * (1.0f + tanhf(u));
}

__device__ __forceinline__ uint32_t smem_u32(const void* p) {
    uint32_t a;
    asm("{ .reg .u64 t; cvta.to.shared.u64 t, %1; cvt.u32.u64 %0, t; }" : "=r"(a) : "l"(p));
    return a;
}

__device__ __forceinline__ void cpasync16(uint32_t s, const void* g) {
    asm volatile("cp.async.cg.shared.global [%0], [%1], 16;" :: "r"(s), "l"(g));
}
#define CP_COMMIT() asm volatile("cp.async.commit_group;" ::: "memory")
#define CP_WAIT0()  asm volatile("cp.async.wait_group 0;" ::: "memory")
#define CP_WAIT1()  asm volatile("cp.async.wait_group 1;" ::: "memory")

__device__ __forceinline__ void mma16816(float* d, const uint32_t* a, const uint32_t* b) {
    asm volatile(
        "mma.sync.aligned.m16n8k16.row.col.f32.f16.f16.f32 "
        "{%0,%1,%2,%3}, {%4,%5,%6,%7}, {%8,%9}, {%0,%1,%2,%3};\n"
        : "+f"(d[0]), "+f"(d[1]), "+f"(d[2]), "+f"(d[3])
        : "r"(a[0]), "r"(a[1]), "r"(a[2]), "r"(a[3]), "r"(b[0]), "r"(b[1]));
}

__device__ __forceinline__ void ldsm4(uint32_t& r0, uint32_t& r1, uint32_t& r2, uint32_t& r3,
                                      uint32_t addr) {
    asm volatile("ldmatrix.sync.aligned.m8n8.x4.shared.b16 {%0,%1,%2,%3}, [%4];"
                 : "=r"(r0), "=r"(r1), "=r"(r2), "=r"(r3) : "r"(addr));
}

// ---------------- zero output ----------------
__global__ void zero_out_kernel(float* __restrict__ out, int n4) {
    int i = blockIdx.x * blockDim.x + threadIdx.x;
    if (i < n4) ((float4*)out)[i] = make_float4(0.f, 0.f, 0.f, 0.f);
}

// ---------------- one-time fp32 -> fp16 conversions ----------------
__global__ void f2h_kernel(const float* __restrict__ in, __half* __restrict__ out, int n4) {
    int i = blockIdx.x * blockDim.x + threadIdx.x;
    if (i < n4) {
        float4 v = ((const float4*)in)[i];
        ((__half2*)out)[2 * i + 0] = __floats2half2_rn(v.x, v.y);
        ((__half2*)out)[2 * i + 1] = __floats2half2_rn(v.z, v.w);
    }
}

// batched transpose: in [R][C] fp32 row-major -> out [C][R] fp16 (z = batch)
__global__ void transpose_f2h(const float* __restrict__ in, __half* __restrict__ out,
                              int R, int C) {
    __shared__ float t[32][33];
    size_t base = (size_t)blockIdx.z * R * C;
    int x = blockIdx.x * 32 + threadIdx.x;
    int y = blockIdx.y * 32 + threadIdx.y;
    #pragma unroll
    for (int j = 0; j < 32; j += 8)
        t[threadIdx.y + j][threadIdx.x] = in[base + (size_t)(y + j) * C + x];
    __syncthreads();
    int ox = blockIdx.y * 32 + threadIdx.x;
    int oy = blockIdx.x * 32 + threadIdx.y;
    #pragma unroll
    for (int j = 0; j < 32; j += 8)
        out[base + (size_t)(oy + j) * R + ox] = __float2half_rn(t[threadIdx.x][threadIdx.y + j]);
}

// ---------------- router: exact fp32, 64x64 tiles (full-chip occupancy) ---
// C[M,N] = relu(A[M,K] @ B[K,N] + bias[N]).  M%64==0, N%64==0, K%16==0.
__global__ void __launch_bounds__(256)
gemm64_bias_relu(const float* __restrict__ A, const float* __restrict__ B,
                 const float* __restrict__ bias, float* __restrict__ C,
                 int M, int N, int K) {
    const int BKr = 16;
    __shared__ float As[BKr][64];
    __shared__ float Bs[BKr][64];
    int tid = threadIdx.x;
    int m0 = blockIdx.y * 64, n0 = blockIdx.x * 64;
    int tx = tid & 15, ty = tid >> 4;
    int arow = tid >> 2, ac4 = (tid & 3) * 4;     // A: 64 rows x 4 float4 per row
    int brow = tid >> 4, bc4 = (tid & 15) * 4;    // B: 16 rows x 16 float4 per row
    float acc[4][4];
    #pragma unroll
    for (int i = 0; i < 4; i++)
        #pragma unroll
        for (int j = 0; j < 4; j++) acc[i][j] = 0.f;

    const float* aptr = A + (size_t)(m0 + arow) * K + ac4;
    const float* bptr = B + (size_t)brow * N + n0 + bc4;
    for (int k0 = 0; k0 < K; k0 += BKr) {
        float4 av = *(const float4*)(aptr + k0);
        As[ac4 + 0][arow] = av.x; As[ac4 + 1][arow] = av.y;
        As[ac4 + 2][arow] = av.z; As[ac4 + 3][arow] = av.w;
        float4 bv = *(const float4*)(bptr + (size_t)k0 * N);
        *(float4*)&Bs[brow][bc4] = bv;
        __syncthreads();
        #pragma unroll
        for (int k = 0; k < BKr; k++) {
            float ra[4], rb[4];
            #pragma unroll
            for (int i = 0; i < 4; i++) ra[i] = As[k][ty * 4 + i];
            #pragma unroll
            for (int j = 0; j < 4; j++) rb[j] = Bs[k][tx * 4 + j];
            #pragma unroll
            for (int i = 0; i < 4; i++)
                #pragma unroll
                for (int j = 0; j < 4; j++) acc[i][j] = fmaf(ra[i], rb[j], acc[i][j]);
        }
        __syncthreads();
    }
    #pragma unroll
    for (int i = 0; i < 4; i++) {
        int m = m0 + ty * 4 + i;
        #pragma unroll
        for (int j = 0; j < 4; j++) {
            int n = n0 + tx * 4 + j;
            C[(size_t)m * N + n] = fmaxf(acc[i][j] + bias[n], 0.f);
        }
    }
}

__global__ void router_final(const float* __restrict__ gw3, float* __restrict__ out_logits) {
    int t = blockIdx.x * blockDim.x + threadIdx.x;
    if (t >= T_TOK) return;
    float l[E_NUM];
    #pragma unroll
    for (int e = 0; e < E_NUM; e++) l[e] = 0.f;
    const float* g = g_g2 + (size_t)t * G2_N;
    for (int k = 0; k < G2_N; k++) {
        float gv = g[k];
        #pragma unroll
        for (int e = 0; e < E_NUM; e++) l[e] = fmaf(gv, gw3[k * E_NUM + e], l[e]);
    }
    #pragma unroll
    for (int e = 0; e < E_NUM; e++) out_logits[(size_t)t * E_NUM + e] = l[e];
    int i0 = 0; float v0 = l[0];
    #pragma unroll
    for (int e = 1; e < E_NUM; e++) { if (l[e] > v0) { v0 = l[e]; i0 = e; } }
    int i1 = -1; float v1 = -3.4e38f;
    #pragma unroll
    for (int e = 0; e < E_NUM; e++) { if (e != i0 && l[e] > v1) { v1 = l[e]; i1 = e; } }
    float e1 = expf(v1 - v0);
    float inv = 1.f / (1.f + e1);
    g_topi[2 * t] = i0;  g_topi[2 * t + 1] = i1;
    g_topw[2 * t] = inv; g_topw[2 * t + 1] = e1 * inv;
}

__global__ void build_pairs() {
    __shared__ int s_cnt[E_NUM];
    __shared__ int s_off[E_NUM];
    int tid = threadIdx.x, wid = tid >> 5, lane = tid & 31;
    if (wid < E_NUM) {
        int e = wid, cnt = 0;
        for (int base = 0; base < T_TOK; base += 32) {
            int t = base + lane;
            bool c = (g_topi[2 * t] == e) || (g_topi[2 * t + 1] == e);
            cnt += __popc(__ballot_sync(0xffffffffu, c));
        }
        if (lane == 0) s_cnt[e] = cnt;
    }
    __syncthreads();
    if (tid == 0) {
        int off = 0;
        for (int e = 0; e < E_NUM; e++) {
            s_off[e] = off; g_offsets[e] = off; g_counts[e] = s_cnt[e];
            off += s_cnt[e];
        }
    }
    __syncthreads();
    if (wid < E_NUM) {
        int e = wid, pos = s_off[e];
        for (int base = 0; base < T_TOK; base += 32) {
            int t = base + lane;
            bool c0 = (g_topi[2 * t] == e);
            bool c  = c0 || (g_topi[2 * t + 1] == e);
            unsigned b = __ballot_sync(0xffffffffu, c);
            int idx = pos + __popc(b & ((1u << lane) - 1u));
            if (c) {
                g_pair_token[idx] = t;
                g_pair_w[idx] = c0 ? g_topw[2 * t] : g_topw[2 * t + 1];
            }
            pos += __popc(b);
        }
    }
}

// ======================================================================
// fp16 mma.sync expert GEMMs, 3-stage cp.async pipeline + ldmatrix.
// CTA tile 128x128, BK=32, 8 warps (2m x 4n), warp tile 64x32.
// Dynamic smem: 3 stages x (A,B) 128x40 halves = 60 KB. 2 CTAs/SM.
// ======================================================================
#define BK   32
#define KPAD 40
#define TILEB (128 * KPAD * 2)            // bytes per operand per stage
#define SMEM_EXP (6 * TILEB)              // 3 stages x (A + B)

// one BK=32 k-tile of MMAs from stage buffers (ldmatrix fragments)
__device__ __forceinline__ void mma_ktile_ldsm(uint32_t aAddr, uint32_t bAddr,
                                               float acc[4][4][4]) {
    #pragma unroll
    for (int kk = 0; kk < BK; kk += 16) {
        uint32_t a[4][4], b[4][2];
        #pragma unroll
        for (int im = 0; im < 4; im++)
            ldsm4(a[im][0], a[im][1], a[im][2], a[im][3],
                  aAddr + (uint32_t)((im * 16 * KPAD + kk) * 2));
        ldsm4(b[0][0], b[0][1], b[1][0], b[1][1], bAddr + (uint32_t)(kk * 2));
        ldsm4(b[2][0], b[2][1], b[3][0], b[3][1],
              bAddr + (uint32_t)((16 * KPAD + kk) * 2));
        #pragma unroll
        for (int im = 0; im < 4; im++)
            #pragma unroll
            for (int jn = 0; jn < 4; jn++)
                mma16816(acc[im][jn], a[im], b[jn]);
    }
}

// ---------------- pass A: act = gelu(gather(hh) @ w1t[e]^T + b1[e]) ------
__global__ void __launch_bounds__(256, 2)
expert_g1_fp16(const __half* __restrict__ w1t, const float* __restrict__ b1) {
    extern __shared__ char smemraw[];
    int gt = blockIdx.y;
    int e = gt >> 5;
    int m0 = (gt & 31) * 128;
    int cnt = g_counts[e];
    if (m0 >= cnt) return;
    int off = g_offsets[e];
    int n0 = blockIdx.x * 128;
    const __half* Bt = w1t + (size_t)e * F_DIM * D_DIM;

    int tid = threadIdx.x, lane = tid & 31, wid = tid >> 5;
    int warp_m = wid & 1, warp_n = wid >> 1;
    uint32_t sa = smem_u32(smemraw);

    // cp.async mapping: 512 16B-chunks per operand tile; 2 per thread
    int c0 = tid * 2, c1 = tid * 2 + 1;
    int ar0 = c0 >> 2, ac0 = c0 & 3;
    int ar1 = c1 >> 2, ac1 = c1 & 3;
    int p0 = (m0 + ar0 < cnt) ? off + m0 + ar0 : off;
    int p1 = (m0 + ar1 < cnt) ? off + m0 + ar1 : off;
    const __half* asrc0 = g_hh + (size_t)g_pair_token[p0] * D_DIM + ac0 * 8;
    const __half* asrc1 = g_hh + (size_t)g_pair_token[p1] * D_DIM + ac1 * 8;
    const __half* bsrc0 = Bt + (size_t)(n0 + ar0) * D_DIM + ac0 * 8;
    const __half* bsrc1 = Bt + (size_t)(n0 + ar1) * D_DIM + ac1 * 8;
    uint32_t adst0 = (uint32_t)(ar0 * KPAD + ac0 * 8) * 2;
    uint32_t adst1 = (uint32_t)(ar1 * KPAD + ac1 * 8) * 2;
    uint32_t bdst0 = 3 * TILEB + (uint32_t)(ar0 * KPAD + ac0 * 8) * 2;
    uint32_t bdst1 = 3 * TILEB + (uint32_t)(ar1 * KPAD + ac1 * 8) * 2;

    // ldmatrix fragment base addresses (per-lane)
    int a_row = lane & 15;
    int a_colh = (lane >> 4) * 8;
    uint32_t aBase = sa + (uint32_t)(((warp_m * 64 + a_row) * KPAD + a_colh) * 2);
    int b_row = (lane & 7) + ((lane >> 4) & 1) * 8;
    int b_colh = ((lane >> 3) & 1) * 8;
    uint32_t bBase = sa + 3 * TILEB + (uint32_t)(((warp_n * 32 + b_row) * KPAD + b_colh) * 2);

    float acc[4][4][4];
    #pragma unroll
    for (int im = 0; im < 4; im++)
        #pragma unroll
        for (int jn = 0; jn < 4; jn++)
            #pragma unroll
            for (int q = 0; q < 4; q++) acc[im][jn][q] = 0.f;

    const int NT = D_DIM / BK;
    // prologue: stages 0,1
    #pragma unroll
    for (int s = 0; s < 2; s++) {
        int kb = s * BK;
        uint32_t so = (uint32_t)s * TILEB;
        cpasync16(sa + so + adst0, asrc0 + kb); cpasync16(sa + so + adst1, asrc1 + kb);
        cpasync16(sa + so + bdst0, bsrc0 + kb); cpasync16(sa + so + bdst1, bsrc1 + kb);
        CP_COMMIT();
    }

    for (int kt = 0; kt < NT; kt++) {
        if (kt + 1 < NT) { CP_WAIT1(); } else { CP_WAIT0(); }
        __syncthreads();
        if (kt + 2 < NT) {
            int s = (kt + 2) % 3;
            int kb = (kt + 2) * BK;
            uint32_t so = (uint32_t)s * TILEB;
            cpasync16(sa + so + adst0, asrc0 + kb); cpasync16(sa + so + adst1, asrc1 + kb);
            cpasync16(sa + so + bdst0, bsrc0 + kb); cpasync16(sa + so + bdst1, bsrc1 + kb);
            CP_COMMIT();
        }
        uint32_t so = (uint32_t)(kt % 3) * TILEB;
        mma_ktile_ldsm(aBase + so, bBase + so, acc);
    }

    // epilogue: gelu(acc + b1) -> g_acth (fp16)
    int g = lane >> 2, t2 = (lane & 3) * 2;
    #pragma unroll
    for (int im = 0; im < 4; im++) {
        #pragma unroll
        for (int hf = 0; hf < 2; hf++) {
            int mloc = warp_m * 64 + im * 16 + g + hf * 8;
            if (m0 + mloc < cnt) {
                size_t pi = (size_t)(off + m0 + mloc);
                #pragma unroll
                for (int jn = 0; jn < 4; jn++) {
                    int n = n0 + warp_n * 32 + jn * 8 + t2;
                    float vx = acc[im][jn][hf * 2 + 0] + b1[e * F_DIM + n + 0];
                    float vy = acc[im][jn][hf * 2 + 1] + b1[e * F_DIM + n + 1];
                    *(__half2*)&g_acth[pi * F_DIM + n] =
                        __floats2half2_rn(gelu_tanh(vx), gelu_tanh(vy));
                }
            }
        }
    }
}

// ---------------- pass B: out[token] += wt * (acth @ w2t[e]^T + b2[e]) ---
__global__ void __launch_bounds__(256, 2)
expert_g2_fp16(const __half* __restrict__ w2t, const float* __restrict__ b2,
               float* __restrict__ out) {
    extern __shared__ char smemraw[];
    int gt = blockIdx.y;
    int e = gt >> 5;
    int m0 = (gt & 31) * 128;
    int cnt = g_counts[e];
    if (m0 >= cnt) return;
    int off = g_offsets[e];
    int n0 = blockIdx.x * 128;
    const __half* Bt = w2t + (size_t)e * D_DIM * F_DIM;

    int tid = threadIdx.x, lane = tid & 31, wid = tid >> 5;
    int warp_m = wid & 1, warp_n = wid >> 1;
    uint32_t sa = smem_u32(smemraw);

    int c0 = tid * 2, c1 = tid * 2 + 1;
    int ar0 = c0 >> 2, ac0 = c0 & 3;
    int ar1 = c1 >> 2, ac1 = c1 & 3;
    size_t p0 = (size_t)((m0 + ar0 < cnt) ? off + m0 + ar0 : off);
    size_t p1 = (size_t)((m0 + ar1 < cnt) ? off + m0 + ar1 : off);
    const __half* asrc0 = g_acth + p0 * F_DIM + ac0 * 8;
    const __half* asrc1 = g_acth + p1 * F_DIM + ac1 * 8;
    const __half* bsrc0 = Bt + (size_t)(n0 + ar0) * F_DIM + ac0 * 8;
    const __half* bsrc1 = Bt + (size_t)(n0 + ar1) * F_DIM + ac1 * 8;
    uint32_t adst0 = (uint32_t)(ar0 * KPAD + ac0 * 8) * 2;
    uint32_t adst1 = (uint32_t)(ar1 * KPAD + ac1 * 8) * 2;
    uint32_t bdst0 = 3 * TILEB + (uint32_t)(ar0 * KPAD + ac0 * 8) * 2;
    uint32_t bdst1 = 3 * TILEB + (uint32_t)(ar1 * KPAD + ac1 * 8) * 2;

    int a_row = lane & 15;
    int a_colh = (lane >> 4) * 8;
    uint32_t aBase = sa + (uint32_t)(((warp_m * 64 + a_row) * KPAD + a_colh) * 2);
    int b_row = (lane & 7) + ((lane >> 4) & 1) * 8;
    int b_colh = ((lane >> 3) & 1) * 8;
    uint32_t bBase = sa + 3 * TILEB + (uint32_t)(((warp_n * 32 + b_row) * KPAD + b_colh) * 2);

    float acc[4][4][4];
    #pragma unroll
    for (int im = 0; im < 4; im++)
        #pragma unroll
        for (int jn = 0; jn < 4; jn++)
            #pragma unroll
            for (int q = 0; q < 4; q++) acc[im][jn][q] = 0.f;

    const int NT = F_DIM / BK;
    #pragma unroll
    for (int s = 0; s < 2; s++) {
        int kb = s * BK;
        uint32_t so = (uint32_t)s * TILEB;
        cpasync16(sa + so + adst0, asrc0 + kb); cpasync16(sa + so + adst1, asrc1 + kb);
        cpasync16(sa + so + bdst0, bsrc0 + kb); cpasync16(sa + so + bdst1, bsrc1 + kb);
        CP_COMMIT();
    }

    for (int kt = 0; kt < NT; kt++) {
        if (kt + 1 < NT) { CP_WAIT1(); } else { CP_WAIT0(); }
        __syncthreads();
        if (kt + 2 < NT) {
            int s = (kt + 2) % 3;
            int kb = (kt + 2) * BK;
            uint32_t so = (uint32_t)s * TILEB;
            cpasync16(sa + so + adst0, asrc0 + kb); cpasync16(sa + so + adst1, asrc1 + kb);
            cpasync16(sa + so + bdst0, bsrc0 + kb); cpasync16(sa + so + bdst1, bsrc1 + kb);
            CP_COMMIT();
        }
        uint32_t so = (uint32_t)(kt % 3) * TILEB;
        mma_ktile_ldsm(aBase + so, bBase + so, acc);
    }

    // epilogue: out[token] += wt * (acc + b2)
    int g = lane >> 2, t2 = (lane & 3) * 2;
    #pragma unroll
    for (int im = 0; im < 4; im++) {
        #pragma unroll
        for (int hf = 0; hf < 2; hf++) {
            int mloc = warp_m * 64 + im * 16 + g + hf * 8;
            if (m0 + mloc < cnt) {
                int pi = off + m0 + mloc;
                int tok = g_pair_token[pi];
                float wt = g_pair_w[pi];
                #pragma unroll
                for (int jn = 0; jn < 4; jn++) {
                    int n = n0 + warp_n * 32 + jn * 8 + t2;
                    float vx = wt * (acc[im][jn][hf * 2 + 0] + b2[e * D_DIM + n + 0]);
                    float vy = wt * (acc[im][jn][hf * 2 + 1] + b2[e * D_DIM + n + 1]);
                    atomicAdd(&out[(size_t)tok * D_DIM + n + 0], vx);
                    atomicAdd(&out[(size_t)tok * D_DIM + n + 1], vy);
                }
            }
        }
    }
}

// ---------------- launch ----------------
extern "C" void kernel_launch(void* const* d_in, const int* in_sizes, int n_in,
                              void* d_out, int out_size) {
    const float* h   = (const float*)d_in[0];
    const float* gw1 = (const float*)d_in[1];
    const float* gb1 = (const float*)d_in[2];
    const float* gw2 = (const float*)d_in[3];
    const float* gb2 = (const float*)d_in[4];
    const float* gw3 = (const float*)d_in[5];
    const float* w1  = (const float*)d_in[6];
    const float* b1  = (const float*)d_in[7];
    const float* w2  = (const float*)d_in[8];
    const float* b2  = (const float*)d_in[9];
    (void)in_sizes; (void)n_in; (void)out_size;

    float* out = (float*)d_out;
    float* out_logits = out + (size_t)T_TOK * D_DIM;

    void *p_g1 = nullptr, *p_g2 = nullptr, *p_hh = nullptr, *p_w1t = nullptr, *p_w2t = nullptr;
    cudaGetSymbolAddress(&p_g1, g_g1);
    cudaGetSymbolAddress(&p_g2, g_g2);
    cudaGetSymbolAddress(&p_hh, g_hh);
    cudaGetSymbolAddress(&p_w1t, g_w1t);
    cudaGetSymbolAddress(&p_w2t, g_w2t);
    float*  g1  = (float*)p_g1;
    float*  g2  = (float*)p_g2;
    __half* hh  = (__half*)p_hh;
    __half* w1t = (__half*)p_w1t;
    __half* w2t = (__half*)p_w2t;

    cudaFuncSetAttribute(expert_g1_fp16, cudaFuncAttributeMaxDynamicSharedMemorySize, SMEM_EXP);
    cudaFuncSetAttribute(expert_g2_fp16, cudaFuncAttributeMaxDynamicSharedMemorySize, SMEM_EXP);

    // zero dense output
    {
        int n4 = T_TOK * D_DIM / 4;
        zero_out_kernel<<<(n4 + 255) / 256, 256>>>(out, n4);
    }
    // one-time conversions / transposes to fp16
    {
        int n4 = T_TOK * D_DIM / 4;
        f2h_kernel<<<(n4 + 255) / 256, 256>>>(h, hh, n4);
        transpose_f2h<<<dim3(F_DIM / 32, D_DIM / 32, E_NUM), dim3(32, 8)>>>(w1, w1t, D_DIM, F_DIM);
        transpose_f2h<<<dim3(D_DIM / 32, F_DIM / 32, E_NUM), dim3(32, 8)>>>(w2, w2t, F_DIM, D_DIM);
    }
    // router (exact fp32) — 64x64 tiles for full-chip occupancy
    gemm64_bias_relu<<<dim3(G1_N / 64, T_TOK / 64), 256>>>(h, gw1, gb1, g1, T_TOK, G1_N, D_DIM);
    gemm64_bias_relu<<<dim3(G2_N / 64, T_TOK / 64), 256>>>(g1, gw2, gb2, g2, T_TOK, G2_N, G1_N);
    router_final<<<T_TOK / 128, 128>>>(gw3, out_logits);
    build_pairs<<<1, 256>>>();
    // experts (fp16 mma.sync + ldmatrix + 3-stage cp.async)
    expert_g1_fp16<<<dim3(F_DIM / 128, E_NUM * 32), 256, SMEM_EXP>>>(w1t, b1);
    expert_g2_fp16<<<dim3(D_DIM / 128, E_NUM * 32), 256, SMEM_EXP>>>(w2t, b2, out);
}